// round 15
// baseline (speedup 1.0000x reference)
#include <cuda_runtime.h>
#include <cuda_fp16.h>
#include <math.h>
#include <stdint.h>

// ---------------- constants ----------------
#define BB 4
#define TT 12
#define BT 48
#define DD 384
#define C2 768
#define NP 12288
#define KC 6912
#define DFF 1536
#define DFF2 3072
#define KENC 1024
#define NDEC 1024
#define LL 4

typedef __half hf;

// ---------------- device scratch ----------------
__device__ float g_Z[(size_t)NP * C2];
__device__ float g_XE[(size_t)NP * C2];
__device__ float g_DEC[(size_t)NP * C2];
__device__ hf g_IM[(size_t)NP * KENC];
__device__ hf g_Ab[(size_t)NP * C2];
__device__ hf g_Zb[(size_t)NP * C2];
__device__ hf g_Fb[(size_t)NP * C2];      // fp16 of final Z (decoder input)
__device__ hf g_Hb[(size_t)NP * DFF2];
__device__ hf g_Wcb[(size_t)LL * C2 * KC];
__device__ hf g_Eb[(size_t)LL * C2 * C2];
__device__ hf g_Eib[(size_t)LL * C2 * C2];
__device__ hf g_W1b[(size_t)LL * DFF2 * C2];   // [N=3072][K=768]
__device__ hf g_W2b[(size_t)LL * C2 * DFF2];   // [N=768][K=3072]
__device__ hf g_encb[C2 * KENC];
__device__ hf g_decb[NDEC * C2];
__device__ float g_Wsbig[(size_t)LL * C2 * C2];
__device__ float g_xmean[BT * C2];
__device__ float g_flux[BT * C2];
__device__ float g_src[BT * C2];
__device__ float g_gate[BT * DD];
__device__ float g_OD[BT * C2];
__device__ float g_OF[BT * C2];

// ---------------- helpers ----------------
__device__ __forceinline__ float softplus_f(float x) {
    return (x > 20.f) ? x : log1pf(expf(x));
}
__device__ __forceinline__ float gelu_tanh(float x) {
    float x3 = x * x * x;
    float t = tanhf(0.7978845608028654f * (x + 0.044715f * x3));
    return 0.5f * x * (1.f + t);
}
__device__ __forceinline__ uint32_t smem_u32(const void* p) {
    uint32_t a;
    asm("{ .reg .u64 t; cvta.to.shared.u64 t, %1; cvt.u32.u64 %0, t; }" : "=r"(a) : "l"(p));
    return a;
}
__device__ __forceinline__ void cp16(uint32_t dst, const void* src) {
    asm volatile("cp.async.cg.shared.global [%0], [%1], 16;" :: "r"(dst), "l"(src) : "memory");
}
__device__ __forceinline__ void cp16z(uint32_t dst, const void* src, uint32_t sz) {
    asm volatile("cp.async.cg.shared.global [%0], [%1], 16, %2;" :: "r"(dst), "l"(src), "r"(sz) : "memory");
}
#define CP_COMMIT() asm volatile("cp.async.commit_group;" ::: "memory")

#define LDSM4(r, addr) \
    asm volatile("ldmatrix.sync.aligned.m8n8.x4.shared.b16 {%0,%1,%2,%3}, [%4];" \
                 : "=r"((r)[0]), "=r"((r)[1]), "=r"((r)[2]), "=r"((r)[3]) : "r"(addr))

#define MMA16816(d, a, bb0, bb1) \
    asm volatile("mma.sync.aligned.m16n8k16.row.col.f32.f16.f16.f32 " \
                 "{%0,%1,%2,%3}, {%4,%5,%6,%7}, {%8,%9}, {%0,%1,%2,%3};" \
                 : "+f"((d)[0]), "+f"((d)[1]), "+f"((d)[2]), "+f"((d)[3]) \
                 : "r"((a)[0]), "r"((a)[1]), "r"((a)[2]), "r"((a)[3]), \
                   "r"(bb0), "r"(bb1))

// ---------------- warp-MMA fp16 GEMM (single product, 3-stage pipeline) ----------------
// C[M=12288, N] = A @ B^T, A and B single fp16.
// Block tile 256x128x32, 8 warps (4M x 2N), warp tile 64x64.
// smem/stage: A 256x80B=20480 + B 128x80B=10240 -> 30720B; x3 stages = 92160B.
// grid: x = N/128 (fast -> A tile L2 reuse), y = M/256 (= one bt per CTA).
// MODE: 0 store, 1 store+bias, 3 acc+bias+hf-emit, 4 gelu->hf, 6 Z-fuse+hf-emit,
//       7 dec-scatter, 8 store + fused hw-rowmean into Xm (spectral GEMM)
// CONV: implicit 3x3 im2col from A [NP][C2] (K = 9*768); spatial math hoisted.
// NOTE: load_chunk takes k0 as an ELEMENT offset (chunk << 5) — cp.async 16B
// alignment depends on it (R11 regression: passing a chunk index misaligns src).
#define MATA_B 20480
#define STAGE_B 30720
#define SMEM_TOTAL_G (3 * STAGE_B)

template <int MODE, bool CONV>
__global__ __launch_bounds__(256) void hgemm_k(
    const hf* __restrict__ A0, const hf* __restrict__ B,
    float* __restrict__ C, hf* __restrict__ C0,
    const float* __restrict__ Caux, const float* __restrict__ bias,
    float* __restrict__ Xm, int N, int K)
{
    extern __shared__ char smem[];
    uint32_t sb = smem_u32(smem);
    const int tid = threadIdx.x;
    const int wid = tid >> 5;
    const int lane = tid & 31;
    const int n0 = blockIdx.x * 128;
    const int m0 = blockIdx.y * 256;
    const int wm = wid & 3;       // 0..3 (M, x64)
    const int wn = wid >> 2;      // 0..1 (N, x64)

    // CONV precompute: per-slot row pointer and spatial coords.
    const hf* rowA[4];
    int hA[4], wA[4];
    if (CONV) {
#pragma unroll
        for (int i = 0; i < 4; i++) {
            int m = m0 + (tid >> 2) + 64 * i;
            hA[i] = (m >> 4) & 15;
            wA[i] = m & 15;
            rowA[i] = A0 + (size_t)m * 768 + (tid & 3) * 8;
        }
    }

    auto load_chunk = [&](int k0, int buf) {
        uint32_t st = sb + buf * STAGE_B;
        if (CONV) {
            int rs = k0 / 768;               // uniform across chunk
            int ci0 = k0 - rs * 768;
            int dy = rs / 3 - 1, dx = rs - (rs / 3) * 3 - 1;
            intptr_t doff = (intptr_t)(dy * 16 + dx) * 768 + ci0;
#pragma unroll
            for (int i = 0; i < 4; i++) {
                uint32_t dst = st + ((tid >> 2) + 64 * i) * 80 + (tid & 3) * 16;
                int hh = hA[i] + dy, ww = wA[i] + dx;
                bool ok = ((unsigned)hh < 16u) && ((unsigned)ww < 16u);
                const hf* sp = ok ? (rowA[i] + doff) : A0;
                cp16z(dst, sp, ok ? 16u : 0u);
            }
        } else {
#pragma unroll
            for (int i = 0; i < 4; i++) {
                int id = tid + 256 * i;
                int row = id >> 2, c4 = id & 3;
                uint32_t dst = st + row * 80 + c4 * 16;
                cp16(dst, A0 + (size_t)(m0 + row) * K + k0 + c4 * 8);
            }
        }
#pragma unroll
        for (int i = 0; i < 2; i++) {
            int id = tid + 256 * i;
            int row = id >> 2, c4 = id & 3;
            uint32_t dst = st + MATA_B + row * 80 + c4 * 16;
            cp16(dst, B + (size_t)(n0 + row) * K + k0 + c4 * 8);
        }
    };

    float acc[4][8][4];
#pragma unroll
    for (int i = 0; i < 4; i++)
#pragma unroll
        for (int j = 0; j < 8; j++)
#pragma unroll
            for (int e = 0; e < 4; e++) acc[i][j][e] = 0.f;

    const int nc = K >> 5;   // all GEMMs have nc >= 24
    load_chunk(0, 0);
    CP_COMMIT();
    load_chunk(32, 1);
    CP_COMMIT();

    const int lrow = lane & 15;
    const int lcol = lane >> 4;

    for (int c = 0; c < nc; c++) {
        int buf = c % 3;
        if (c + 2 < nc) {
            load_chunk((c + 2) << 5, (c + 2) % 3);
            CP_COMMIT();
            asm volatile("cp.async.wait_group 2;" ::: "memory");
        } else if (c + 1 < nc) {
            asm volatile("cp.async.wait_group 1;" ::: "memory");
        } else {
            asm volatile("cp.async.wait_group 0;" ::: "memory");
        }
        __syncthreads();
        uint32_t st = sb + buf * STAGE_B;
#pragma unroll
        for (int ks = 0; ks < 2; ks++) {
            uint32_t a0[4][4];
#pragma unroll
            for (int mi = 0; mi < 4; mi++) {
                uint32_t ad = st + (wm * 64 + mi * 16 + lrow) * 80 + ks * 32 + lcol * 16;
                LDSM4(a0[mi], ad);
            }
#pragma unroll
            for (int nq = 0; nq < 4; nq++) {
                uint32_t br[4];
                uint32_t bd = st + MATA_B + (wn * 64 + nq * 16 + lrow) * 80 + ks * 32 + lcol * 16;
                LDSM4(br, bd);
#pragma unroll
                for (int mi = 0; mi < 4; mi++) {
                    MMA16816(acc[mi][nq * 2],     a0[mi], br[0], br[2]);
                    MMA16816(acc[mi][nq * 2 + 1], a0[mi], br[1], br[3]);
                }
            }
        }
        __syncthreads();
    }

    // per-thread column partial sums for MODE 8 (16 col slots: nj*2 + {0,1})
    float lsum[16];
    if (MODE == 8) {
#pragma unroll
        for (int i = 0; i < 16; i++) lsum[i] = 0.f;
    }

    // epilogue (vectorized: float2 / half2)
#pragma unroll
    for (int mi = 0; mi < 4; mi++) {
#pragma unroll
        for (int nj = 0; nj < 8; nj++) {
            int row = m0 + wm * 64 + mi * 16 + (lane >> 2);
            int col = n0 + wn * 64 + nj * 8 + (lane & 3) * 2;
            float* d = acc[mi][nj];
#pragma unroll
            for (int h = 0; h < 2; h++) {
                int r = row + h * 8;
                float v0 = d[h * 2 + 0], v1 = d[h * 2 + 1];
                if (MODE == 1 || MODE == 3 || MODE == 7) {
                    v0 += bias[col];
                    v1 += bias[col + 1];
                }
                size_t co = (size_t)r * N + col;
                if (MODE == 0 || MODE == 1) {
                    *(float2*)(C + co) = make_float2(v0, v1);
                } else if (MODE == 8) {
                    *(float2*)(C + co) = make_float2(v0, v1);
                    lsum[nj * 2 + 0] += v0;
                    lsum[nj * 2 + 1] += v1;
                } else if (MODE == 3) {
                    float2 zc = *(const float2*)(C + co);
                    float z0 = zc.x + v0, z1 = zc.y + v1;
                    *(float2*)(C + co) = make_float2(z0, z1);
                    *(__half2*)(C0 + co) = __floats2half2_rn(z0, z1);
                } else if (MODE == 4) {
                    *(__half2*)(C0 + co) = __floats2half2_rn(gelu_tanh(v0), gelu_tanh(v1));
                } else if (MODE == 6) {
                    float2 ax = *(const float2*)(Caux + co);
                    float2 zc = *(const float2*)(C + co);
                    float z0 = zc.x + ax.x + v0, z1 = zc.y + ax.y + v1;
                    *(float2*)(C + co) = make_float2(z0, z1);
                    *(__half2*)(C0 + co) = __floats2half2_rn(z0, z1);
                } else if (MODE == 7) {
                    // pixel-shuffle scatter: r -> (bt,hp,wp), col -> (co4,pi,pj)
                    int bt = r >> 8;
                    int hp = (r >> 4) & 15, wp = r & 15;
                    int co4 = col >> 8;
                    int rem = col & 255;
                    int pi = rem >> 4, pj = rem & 15;
                    size_t o = (((size_t)(bt * 4 + co4) * 256 + hp * 16 + pi) * 256) + wp * 16 + pj;
                    *(float2*)(C + o) = make_float2(v0, v1);
                }
            }
        }
    }

    if (MODE == 8) {
        // CTA covers exactly one bt (M tile = 256 rows = all hw of blockIdx.y)
        // and a disjoint 128-col slice -> reduction is CTA-local, store direct.
        float* xs = (float*)smem;   // stage buffers no longer needed
        __syncthreads();
        if (tid < 128) xs[tid] = 0.f;
        __syncthreads();
        int cb = wn * 64 + (lane & 3) * 2;
#pragma unroll
        for (int nj = 0; nj < 8; nj++) {
            atomicAdd(&xs[cb + nj * 8], lsum[nj * 2]);
            atomicAdd(&xs[cb + nj * 8 + 1], lsum[nj * 2 + 1]);
        }
        __syncthreads();
        if (tid < 128)
            Xm[(size_t)blockIdx.y * C2 + n0 + tid] = xs[tid] * (1.f / 256.f);
    }
}

// ---------------- tiny fp32 GEMM (M=48) ----------------
__global__ void gemm_small_k(const float* __restrict__ A, const float* __restrict__ B,
                             float* __restrict__ C, int M, int N, int K)
{
    int idx = blockIdx.x * blockDim.x + threadIdx.x;
    if (idx >= M * N) return;
    int m = idx / N, n = idx % N;
    float s = 0.f;
    for (int k = 0; k < K; k++) s += A[(size_t)m * K + k] * B[(size_t)k * N + n];
    C[idx] = s;
}

// ---------------- weight builders (batched over layers) ----------------
__global__ void build_cbig_k(float* __restrict__ dst, const float* __restrict__ re,
                             const float* __restrict__ im, int Kd, int Nd)
{
    int l = blockIdx.y;
    dst += (size_t)l * (4 * Kd * Nd);
    re += (size_t)l * Kd * Nd;
    im += (size_t)l * Kd * Nd;
    int idx = blockIdx.x * blockDim.x + threadIdx.x;
    int N2 = 2 * Nd;
    if (idx >= 2 * Kd * N2) return;
    int k2 = idx / N2, n2 = idx % N2;
    bool ki = k2 >= Kd, ni = n2 >= Nd;
    int k = ki ? k2 - Kd : k2;
    int n = ni ? n2 - Nd : n2;
    float v;
    if (!ki && !ni) v = re[(size_t)k * Nd + n];
    else if (!ki && ni) v = im[(size_t)k * Nd + n];
    else if (ki && !ni) v = -im[(size_t)k * Nd + n];
    else v = re[(size_t)k * Nd + n];
    dst[idx] = v;
}

__global__ void build_cbigT_tile_k(hf* __restrict__ d0,
                                   const float* __restrict__ re, const float* __restrict__ im,
                                   int Kd, int Nd)
{
    __shared__ float tile[32][33];
    int l = blockIdx.z;
    d0 += (size_t)l * (4 * Kd * Nd);
    re += (size_t)l * Kd * Nd;
    im += (size_t)l * Kd * Nd;
    int k2_0 = blockIdx.x * 32, n2_0 = blockIdx.y * 32;
    bool ki = k2_0 >= Kd, ni = n2_0 >= Nd;
    int k0 = k2_0 - (ki ? Kd : 0), n0 = n2_0 - (ni ? Nd : 0);
    const float* s = (ki != ni) ? im : re;
    float sign = (ki && !ni) ? -1.f : 1.f;
    int tx = threadIdx.x, ty = threadIdx.y;
#pragma unroll
    for (int j = 0; j < 4; j++) {
        int r = ty + j * 8;
        tile[r][tx] = s[(size_t)(k0 + r) * Nd + n0 + tx];
    }
    __syncthreads();
    int K2 = 2 * Kd;
#pragma unroll
    for (int j = 0; j < 4; j++) {
        int r = ty + j * 8;
        float v = sign * tile[tx][r];
        d0[(size_t)(n2_0 + r) * K2 + k2_0 + tx] = __float2half(v);
    }
}

__global__ void build_convwT_k(hf* __restrict__ d0, const float* __restrict__ cw)
{
    __shared__ float s[KC];
    int co = blockIdx.x, l = blockIdx.y;
    const float* srcr = cw + ((size_t)(l * C2 + co)) * KC;
    for (int i = threadIdx.x; i < KC; i += 256) s[i] = srcr[i];
    __syncthreads();
    size_t base = ((size_t)l * C2 + co) * KC;
    for (int k = threadIdx.x; k < KC; k += 256) {
        int rs = k / 768;
        int ci = k - rs * 768;
        d0[base + k] = __float2half(s[ci * 9 + rs]);
    }
}

__global__ void cvt4_k(const float* __restrict__ src, hf* __restrict__ d0, size_t n4)
{
    size_t idx = (size_t)blockIdx.x * blockDim.x + threadIdx.x;
    if (idx >= n4) return;
    float4 v = ((const float4*)src)[idx];
    __half2 p0 = {__float2half(v.x), __float2half(v.y)};
    __half2 p1 = {__float2half(v.z), __float2half(v.w)};
    ((__half2*)d0)[idx * 2] = p0;
    ((__half2*)d0)[idx * 2 + 1] = p1;
}

// ---------------- encoder im2col (vectorized x4, fp16) ----------------
__global__ void enc_im2col4_k(hf* __restrict__ P0, const float* __restrict__ x)
{
    size_t idx = (size_t)blockIdx.x * blockDim.x + threadIdx.x;  // NP*KENC/4
    size_t flat = idx * 4;
    int kk = flat % KENC;
    int n = flat / KENC;
    int cin = kk >> 8;
    int ii = (kk >> 4) & 15;
    int jj = kk & 15;
    int bt = n >> 8;
    int ph = (n >> 4) & 15;
    int pw = n & 15;
    const float* xp = x + ((((size_t)(bt * 4 + cin) * 256) + ph * 16 + ii) * 256 + pw * 16 + jj);
    float4 v = *(const float4*)xp;
    __half2 p0 = {__float2half(v.x), __float2half(v.y)};
    __half2 p1 = {__float2half(v.z), __float2half(v.w)};
    ((__half2*)P0)[idx * 2] = p0;
    ((__half2*)P0)[idx * 2 + 1] = p1;
}

// ---------------- layernorm over 768 channels, emits fp16 ----------------
__global__ void layernorm_k(const float* __restrict__ X, const float* __restrict__ g,
                            const float* __restrict__ b, hf* __restrict__ Y0)
{
    __shared__ float red[256];
    int n = blockIdx.x;
    int tid = threadIdx.x;
    const float* x = X + (size_t)n * C2;
    float v0 = x[tid], v1 = x[tid + 256], v2 = x[tid + 512];
    red[tid] = v0 + v1 + v2;
    __syncthreads();
    for (int off = 128; off > 0; off >>= 1) {
        if (tid < off) red[tid] += red[tid + off];
        __syncthreads();
    }
    float m = red[0] * (1.f / 768.f);
    __syncthreads();
    float d0 = v0 - m, d1 = v1 - m, d2 = v2 - m;
    red[tid] = d0 * d0 + d1 * d1 + d2 * d2;
    __syncthreads();
    for (int off = 128; off > 0; off >>= 1) {
        if (tid < off) red[tid] += red[tid + off];
        __syncthreads();
    }
    float var = red[0] * (1.f / 768.f);
    float rstd = rsqrtf(var + 1e-5f);
    size_t base = (size_t)n * C2;
    Y0[base + tid]       = __float2half(d0 * rstd * g[tid] + b[tid]);
    Y0[base + tid + 256] = __float2half(d1 * rstd * g[tid + 256] + b[tid + 256]);
    Y0[base + tid + 512] = __float2half(d2 * rstd * g[tid + 512] + b[tid + 512]);
}

// ---------------- flux scan + gate + op_decay/op_forcing (merged) ----------------
__global__ void fluxscan_k(const float* __restrict__ xm, const float* __restrict__ dt,
                           const float* __restrict__ lamf_p, const float* __restrict__ Wg,
                           const float* __restrict__ nu, const float* __restrict__ omega,
                           float* __restrict__ flux, float* __restrict__ gate,
                           float* __restrict__ OD, float* __restrict__ OF)
{
    int tid = blockIdx.x * blockDim.x + threadIdx.x;  // BB*DD = 1536
    int b = tid / DD, e = tid % DD;
    float lamf = softplus_f(lamf_p[e]);
    float wg = Wg[e];
    float sp = softplus_f(nu[e]);
    float lr = fminf(fmaxf(-sp, -5.f), 0.3f);
    float li = omega[e];
    float den = lr * lr + li * li;
    float fr = 0.f, fi = 0.f;
    for (int t = 0; t < TT; t++) {
        int bt = b * TT + t;
        float dtv = dt[bt];
        // flux scan
        float a = expf(-lamf * dtv);
        float xr = xm[bt * C2 + e] * dtv;
        float xi = xm[bt * C2 + DD + e] * dtv;
        fr = fr * a + xr;
        fi = fi * a + xi;
        flux[bt * C2 + e] = fr;
        flux[bt * C2 + DD + e] = fi;
        gate[bt * DD + e] = 1.f / (1.f + expf(-fr * wg));
        // op decay / forcing
        float er = expf(lr * dtv);
        float odr = er * cosf(li * dtv);
        float odi = er * sinf(li * dtv);
        OD[bt * C2 + e] = odr;
        OD[bt * C2 + DD + e] = odi;
        float nr = odr - 1.f, ni = odi;
        OF[bt * C2 + e] = (nr * lr + ni * li) / den;
        OF[bt * C2 + DD + e] = (ni * lr - nr * li) / den;
    }
}

// ---------------- fused forcing + u scan, emits fp16 ----------------
__global__ void fuscan_k(const float* __restrict__ XE, const float* __restrict__ gate,
                         const float* __restrict__ src, const float* __restrict__ OF,
                         const float* __restrict__ OD, hf* __restrict__ U0)
{
    int tid = blockIdx.x * blockDim.x + threadIdx.x;  // BB*256*DD
    int e = tid % DD;
    int hw = (tid / DD) & 255;
    int b = tid / (DD * 256);
    float ur = 0.f, ui = 0.f;
    for (int t = 0; t < TT; t++) {
        int bt = b * TT + t;
        size_t base = (size_t)(bt * 256 + hw) * C2;
        float xr = XE[base + e], xi = XE[base + DD + e];
        float g = gate[bt * DD + e];
        float sr = src[bt * C2 + e], si = src[bt * C2 + DD + e];
        float fr = xr * g + sr * (1.f - g);
        float fi = xi * g + si * (1.f - g);
        float ofr = OF[bt * C2 + e], ofi = OF[bt * C2 + DD + e];
        float utr = fr * ofr - fi * ofi;
        float uti = fr * ofi + fi * ofr;
        float odr = OD[bt * C2 + e], odi = OD[bt * C2 + DD + e];
        float nr = ur * odr - ui * odi + utr;
        float ni = ur * odi + ui * odr + uti;
        ur = nr; ui = ni;
        U0[base + e] = __float2half(ur);
        U0[base + DD + e] = __float2half(ui);
    }
}

// ---------------- host side ----------------
template <typename T>
static T* sym(const void* s)
{
    void* p = nullptr;
    cudaGetSymbolAddress(&p, s);
    return (T*)p;
}

template <int MODE, bool CONV>
static void launch_gemm(const hf* A0, const hf* B,
                        float* C, hf* C0, const float* Caux,
                        const float* bias, float* Xm, int N, int K)
{
    cudaFuncSetAttribute(hgemm_k<MODE, CONV>, cudaFuncAttributeMaxDynamicSharedMemorySize, SMEM_TOTAL_G);
    dim3 grid(N / 128, NP / 256);
    hgemm_k<MODE, CONV><<<grid, 256, SMEM_TOTAL_G>>>(A0, B, C, C0, Caux, bias, Xm, N, K);
}

extern "C" void kernel_launch(void* const* d_in, const int* in_sizes, int n_in,
                              void* d_out, int out_size)
{
    const float* x       = (const float*)d_in[0];
    const float* dt      = (const float*)d_in[1];
    const float* enc_w   = (const float*)d_in[2];
    const float* enc_b   = (const float*)d_in[3];
    const float* ns_g    = (const float*)d_in[4];
    const float* ns_b    = (const float*)d_in[5];
    const float* cw      = (const float*)d_in[6];
    const float* cb      = (const float*)d_in[7];
    const float* nt_g    = (const float*)d_in[8];
    const float* nt_b    = (const float*)d_in[9];
    const float* E_re    = (const float*)d_in[10];
    const float* E_im    = (const float*)d_in[11];
    const float* Ei_re   = (const float*)d_in[12];
    const float* Ei_im   = (const float*)d_in[13];
    const float* lamflux = (const float*)d_in[14];
    const float* Ws_re   = (const float*)d_in[15];
    const float* Ws_im   = (const float*)d_in[16];
    const float* Wg      = (const float*)d_in[17];
    const float* nu      = (const float*)d_in[18];
    const float* omega   = (const float*)d_in[19];
    const float* w1_re   = (const float*)d_in[20];
    const float* w1_im   = (const float*)d_in[21];
    const float* w2_re   = (const float*)d_in[22];
    const float* w2_im   = (const float*)d_in[23];
    const float* dec_w   = (const float*)d_in[24];
    const float* dec_b   = (const float*)d_in[25];
    float* out = (float*)d_out;

    float* Z   = sym<float>(g_Z);
    float* XE  = sym<float>(g_XE);
    float* DEC = sym<float>(g_DEC);
    hf* IM   = sym<hf>(g_IM);
    hf* Ab   = sym<hf>(g_Ab);
    hf* Zb   = sym<hf>(g_Zb);
    hf* Fb   = sym<hf>(g_Fb);
    hf* Hb   = sym<hf>(g_Hb);
    hf* Wcb  = sym<hf>(g_Wcb);
    hf* Eb   = sym<hf>(g_Eb);
    hf* Eib  = sym<hf>(g_Eib);
    hf* W1b  = sym<hf>(g_W1b);
    hf* W2b  = sym<hf>(g_W2b);
    hf* encb = sym<hf>(g_encb);
    hf* decb = sym<hf>(g_decb);
    float* Wsb  = sym<float>(g_Wsbig);
    float* xm   = sym<float>(g_xmean);
    float* flux = sym<float>(g_flux);
    float* src  = sym<float>(g_src);
    float* gate = sym<float>(g_gate);
    float* OD   = sym<float>(g_OD);
    float* OF   = sym<float>(g_OF);

    // ---- build weights (batched across layers) ----
    {
        dim3 blk(32, 8);
        build_cbigT_tile_k<<<dim3(C2 / 32, C2 / 32, LL), blk>>>(Eb, E_re, E_im, DD, DD);
        build_cbigT_tile_k<<<dim3(C2 / 32, C2 / 32, LL), blk>>>(Eib, Ei_re, Ei_im, DD, DD);
        build_cbig_k<<<dim3((C2 * C2) / 256, LL), 256>>>(Wsb, Ws_re, Ws_im, DD, DD);
        build_cbigT_tile_k<<<dim3(C2 / 32, DFF2 / 32, LL), blk>>>(W1b, w1_re, w1_im, DD, DFF);
        build_cbigT_tile_k<<<dim3(DFF2 / 32, C2 / 32, LL), blk>>>(W2b, w2_re, w2_im, DFF, DD);
        build_convwT_k<<<dim3(C2, LL), 256>>>(Wcb, cw);
        cvt4_k<<<(C2 * KENC / 4 + 255) / 256, 256>>>(enc_w, encb, (size_t)C2 * KENC / 4);
        cvt4_k<<<(NDEC * C2 / 4 + 255) / 256, 256>>>(dec_w, decb, (size_t)NDEC * C2 / 4);
    }

    // ---- encoder ----
    enc_im2col4_k<<<((size_t)NP * KENC / 4) / 256, 256>>>(IM, x);
    launch_gemm<1, false>(IM, encb, Z, nullptr, nullptr, enc_b, nullptr, C2, KENC);

    for (int l = 0; l < LL; l++) {
        // spatial: LN -> implicit conv3x3 GEMM; Z += conv+cb, emit Zb fp16
        layernorm_k<<<NP, 256>>>(Z, ns_g + l * C2, ns_b + l * C2, Ab);
        launch_gemm<3, true>(Ab, Wcb + (size_t)l * C2 * KC, Z, Zb, nullptr, cb + l * C2, nullptr, C2, KC);

        // spectral: XE = Z @ E  (+ fused hw-rowmean -> xm)
        launch_gemm<8, false>(Zb, Eb + (size_t)l * C2 * C2, XE, nullptr, nullptr, nullptr, xm, C2, C2);

        // temporal flux path (fluxscan merged with opdecay)
        fluxscan_k<<<6, 256>>>(xm, dt, lamflux + l * DD, Wg + l * DD, nu + l * DD, omega + l * DD,
                               flux, gate, OD, OF);
        gemm_small_k<<<(BT * C2) / 256, 256>>>(flux, Wsb + (size_t)l * C2 * C2, src, BT, C2, C2);
        fuscan_k<<<(BB * 256 * DD) / 256, 256>>>(XE, gate, src, OF, OD, Ab);

        // decode back: DEC = u_out @ Ei
        launch_gemm<0, false>(Ab, Eib + (size_t)l * C2 * C2, DEC, nullptr, nullptr, nullptr, nullptr, C2, C2);

        // MLP on LN(DEC); Z += DEC + delta (fused, also emits fp16(Z) -> Fb)
        layernorm_k<<<NP, 256>>>(DEC, nt_g + l * C2, nt_b + l * C2, Zb);
        launch_gemm<4, false>(Zb, W1b + (size_t)l * DFF2 * C2, nullptr, Hb, nullptr, nullptr, nullptr, DFF2, C2);
        launch_gemm<6, false>(Hb, W2b + (size_t)l * C2 * DFF2, Z, Fb, DEC, nullptr, nullptr, C2, DFF2);
    }

    // ---- decoder GEMM with fused pixel-shuffle scatter (input: Fb from last Z-fuse) ----
    launch_gemm<7, false>(Fb, decb, out, nullptr, nullptr, dec_b, nullptr, NDEC, C2);

    (void)in_sizes; (void)n_in; (void)out_size;
}

// round 16
// speedup vs baseline: 1.0165x; 1.0165x over previous
#include <cuda_runtime.h>
#include <cuda_fp16.h>
#include <math.h>
#include <stdint.h>

// ---------------- constants ----------------
#define BB 4
#define TT 12
#define BT 48
#define DD 384
#define C2 768
#define NP 12288
#define KC 6912
#define DFF 1536
#define DFF2 3072
#define KENC 1024
#define NDEC 1024
#define LL 4

typedef __half hf;

// ---------------- device scratch ----------------
__device__ float g_Z[(size_t)NP * C2];
__device__ float g_XE[(size_t)NP * C2];
__device__ float g_DEC[(size_t)NP * C2];
__device__ hf g_IM[(size_t)NP * KENC];
__device__ hf g_Ab[(size_t)NP * C2];
__device__ hf g_Zb[(size_t)NP * C2];
__device__ hf g_Fb[(size_t)NP * C2];      // fp16 of final Z (decoder input)
__device__ hf g_Hb[(size_t)NP * DFF2];
__device__ hf g_Wcb[(size_t)LL * C2 * KC];
__device__ hf g_Eb[(size_t)LL * C2 * C2];
__device__ hf g_Eib[(size_t)LL * C2 * C2];
__device__ hf g_W1b[(size_t)LL * DFF2 * C2];   // [N=3072][K=768]
__device__ hf g_W2b[(size_t)LL * C2 * DFF2];   // [N=768][K=3072]
__device__ hf g_encb[C2 * KENC];
__device__ hf g_decb[NDEC * C2];
__device__ float g_Wsbig[(size_t)LL * C2 * C2];
__device__ float g_xmean[BT * C2];
__device__ float g_flux[BT * C2];
__device__ float g_src[BT * C2];
__device__ float g_gate[BT * DD];
__device__ float g_OD[BT * C2];
__device__ float g_OF[BT * C2];

// ---------------- helpers ----------------
__device__ __forceinline__ float softplus_f(float x) {
    return (x > 20.f) ? x : log1pf(expf(x));
}
__device__ __forceinline__ float gelu_tanh(float x) {
    float x3 = x * x * x;
    float t = tanhf(0.7978845608028654f * (x + 0.044715f * x3));
    return 0.5f * x * (1.f + t);
}
__device__ __forceinline__ uint32_t smem_u32(const void* p) {
    uint32_t a;
    asm("{ .reg .u64 t; cvta.to.shared.u64 t, %1; cvt.u32.u64 %0, t; }" : "=r"(a) : "l"(p));
    return a;
}
__device__ __forceinline__ void cp16(uint32_t dst, const void* src) {
    asm volatile("cp.async.cg.shared.global [%0], [%1], 16;" :: "r"(dst), "l"(src) : "memory");
}
__device__ __forceinline__ void cp16z(uint32_t dst, const void* src, uint32_t sz) {
    asm volatile("cp.async.cg.shared.global [%0], [%1], 16, %2;" :: "r"(dst), "l"(src), "r"(sz) : "memory");
}
#define CP_COMMIT() asm volatile("cp.async.commit_group;" ::: "memory")

#define LDSM4(r, addr) \
    asm volatile("ldmatrix.sync.aligned.m8n8.x4.shared.b16 {%0,%1,%2,%3}, [%4];" \
                 : "=r"((r)[0]), "=r"((r)[1]), "=r"((r)[2]), "=r"((r)[3]) : "r"(addr))

#define MMA16816(d, a, bb0, bb1) \
    asm volatile("mma.sync.aligned.m16n8k16.row.col.f32.f16.f16.f32 " \
                 "{%0,%1,%2,%3}, {%4,%5,%6,%7}, {%8,%9}, {%0,%1,%2,%3};" \
                 : "+f"((d)[0]), "+f"((d)[1]), "+f"((d)[2]), "+f"((d)[3]) \
                 : "r"((a)[0]), "r"((a)[1]), "r"((a)[2]), "r"((a)[3]), \
                   "r"(bb0), "r"(bb1))

// ---------------- warp-MMA fp16 GEMM (single product, 3-stage, 1 barrier/chunk) ----------------
// C[M=12288, N] = A @ B^T, A and B single fp16.
// Block tile 256x128x32, 8 warps (4M x 2N), warp tile 64x64.
// smem/stage: A 256x80B=20480 + B 128x80B=10240 -> 30720B; x3 stages = 92160B.
// grid: x = N/128 (fast -> A tile L2 reuse), y = M/256.
// Pipeline invariant (single barrier): at iter c, wait_group(1) proves group c
// complete (only c+1 may be pending); the barrier publishes buf c AND orders
// iter c-1's LDSM reads of buf (c-1)%3 before this iter's cp.async writes to
// buf (c+2)%3 == (c-1)%3. Loads are issued AFTER the barrier.
// MODE: 0 store, 1 store+bias, 3 acc+bias+hf-emit, 4 gelu->hf, 6 Z-fuse+hf-emit, 7 dec-scatter
// CONV: implicit 3x3 im2col from A [NP][C2] (K = 9*768); spatial math hoisted.
// NOTE: load_chunk takes k0 as an ELEMENT offset (chunk << 5) — cp.async 16B
// alignment depends on it (R11 regression: passing a chunk index misaligns src).
#define MATA_B 20480
#define STAGE_B 30720
#define SMEM_TOTAL_G (3 * STAGE_B)

template <int MODE, bool CONV>
__global__ __launch_bounds__(256) void hgemm_k(
    const hf* __restrict__ A0, const hf* __restrict__ B,
    float* __restrict__ C, hf* __restrict__ C0,
    const float* __restrict__ Caux, const float* __restrict__ bias, int N, int K)
{
    extern __shared__ char smem[];
    uint32_t sb = smem_u32(smem);
    const int tid = threadIdx.x;
    const int wid = tid >> 5;
    const int lane = tid & 31;
    const int n0 = blockIdx.x * 128;
    const int m0 = blockIdx.y * 256;
    const int wm = wid & 3;       // 0..3 (M, x64)
    const int wn = wid >> 2;      // 0..1 (N, x64)

    // CONV precompute: per-slot row pointer and spatial coords.
    const hf* rowA[4];
    int hA[4], wA[4];
    if (CONV) {
#pragma unroll
        for (int i = 0; i < 4; i++) {
            int m = m0 + (tid >> 2) + 64 * i;
            hA[i] = (m >> 4) & 15;
            wA[i] = m & 15;
            rowA[i] = A0 + (size_t)m * 768 + (tid & 3) * 8;
        }
    }

    auto load_chunk = [&](int k0, int buf) {
        uint32_t st = sb + buf * STAGE_B;
        if (CONV) {
            int rs = k0 / 768;               // uniform across chunk
            int ci0 = k0 - rs * 768;
            int dy = rs / 3 - 1, dx = rs - (rs / 3) * 3 - 1;
            intptr_t doff = (intptr_t)(dy * 16 + dx) * 768 + ci0;
#pragma unroll
            for (int i = 0; i < 4; i++) {
                uint32_t dst = st + ((tid >> 2) + 64 * i) * 80 + (tid & 3) * 16;
                int hh = hA[i] + dy, ww = wA[i] + dx;
                bool ok = ((unsigned)hh < 16u) && ((unsigned)ww < 16u);
                const hf* sp = ok ? (rowA[i] + doff) : A0;
                cp16z(dst, sp, ok ? 16u : 0u);
            }
        } else {
#pragma unroll
            for (int i = 0; i < 4; i++) {
                int id = tid + 256 * i;
                int row = id >> 2, c4 = id & 3;
                uint32_t dst = st + row * 80 + c4 * 16;
                cp16(dst, A0 + (size_t)(m0 + row) * K + k0 + c4 * 8);
            }
        }
#pragma unroll
        for (int i = 0; i < 2; i++) {
            int id = tid + 256 * i;
            int row = id >> 2, c4 = id & 3;
            uint32_t dst = st + MATA_B + row * 80 + c4 * 16;
            cp16(dst, B + (size_t)(n0 + row) * K + k0 + c4 * 8);
        }
    };

    float acc[4][8][4];
#pragma unroll
    for (int i = 0; i < 4; i++)
#pragma unroll
        for (int j = 0; j < 8; j++)
#pragma unroll
            for (int e = 0; e < 4; e++) acc[i][j][e] = 0.f;

    const int nc = K >> 5;   // all GEMMs have nc >= 24
    load_chunk(0, 0);
    CP_COMMIT();
    load_chunk(32, 1);
    CP_COMMIT();

    const int lrow = lane & 15;
    const int lcol = lane >> 4;

    for (int c = 0; c < nc; c++) {
        int buf = c % 3;
        if (c + 1 < nc) {
            asm volatile("cp.async.wait_group 1;" ::: "memory");
        } else {
            asm volatile("cp.async.wait_group 0;" ::: "memory");
        }
        __syncthreads();
        if (c + 2 < nc) {
            load_chunk((c + 2) << 5, (c + 2) % 3);
            CP_COMMIT();
        }
        uint32_t st = sb + buf * STAGE_B;
#pragma unroll
        for (int ks = 0; ks < 2; ks++) {
            uint32_t a0[4][4];
#pragma unroll
            for (int mi = 0; mi < 4; mi++) {
                uint32_t ad = st + (wm * 64 + mi * 16 + lrow) * 80 + ks * 32 + lcol * 16;
                LDSM4(a0[mi], ad);
            }
#pragma unroll
            for (int nq = 0; nq < 4; nq++) {
                uint32_t br[4];
                uint32_t bd = st + MATA_B + (wn * 64 + nq * 16 + lrow) * 80 + ks * 32 + lcol * 16;
                LDSM4(br, bd);
#pragma unroll
                for (int mi = 0; mi < 4; mi++) {
                    MMA16816(acc[mi][nq * 2],     a0[mi], br[0], br[2]);
                    MMA16816(acc[mi][nq * 2 + 1], a0[mi], br[1], br[3]);
                }
            }
        }
    }

    // epilogue (vectorized: float2 / half2)
#pragma unroll
    for (int mi = 0; mi < 4; mi++) {
#pragma unroll
        for (int nj = 0; nj < 8; nj++) {
            int row = m0 + wm * 64 + mi * 16 + (lane >> 2);
            int col = n0 + wn * 64 + nj * 8 + (lane & 3) * 2;
            float* d = acc[mi][nj];
#pragma unroll
            for (int h = 0; h < 2; h++) {
                int r = row + h * 8;
                float v0 = d[h * 2 + 0], v1 = d[h * 2 + 1];
                if (MODE == 1 || MODE == 3 || MODE == 7) {
                    v0 += bias[col];
                    v1 += bias[col + 1];
                }
                size_t co = (size_t)r * N + col;
                if (MODE == 0 || MODE == 1) {
                    *(float2*)(C + co) = make_float2(v0, v1);
                } else if (MODE == 3) {
                    float2 zc = *(const float2*)(C + co);
                    float z0 = zc.x + v0, z1 = zc.y + v1;
                    *(float2*)(C + co) = make_float2(z0, z1);
                    *(__half2*)(C0 + co) = __floats2half2_rn(z0, z1);
                } else if (MODE == 4) {
                    *(__half2*)(C0 + co) = __floats2half2_rn(gelu_tanh(v0), gelu_tanh(v1));
                } else if (MODE == 6) {
                    float2 ax = *(const float2*)(Caux + co);
                    float2 zc = *(const float2*)(C + co);
                    float z0 = zc.x + ax.x + v0, z1 = zc.y + ax.y + v1;
                    *(float2*)(C + co) = make_float2(z0, z1);
                    *(__half2*)(C0 + co) = __floats2half2_rn(z0, z1);
                } else if (MODE == 7) {
                    // pixel-shuffle scatter: r -> (bt,hp,wp), col -> (co4,pi,pj)
                    int bt = r >> 8;
                    int hp = (r >> 4) & 15, wp = r & 15;
                    int co4 = col >> 8;
                    int rem = col & 255;
                    int pi = rem >> 4, pj = rem & 15;
                    size_t o = (((size_t)(bt * 4 + co4) * 256 + hp * 16 + pi) * 256) + wp * 16 + pj;
                    *(float2*)(C + o) = make_float2(v0, v1);
                }
            }
        }
    }
}

// ---------------- tiny fp32 GEMM (M=48) ----------------
__global__ void gemm_small_k(const float* __restrict__ A, const float* __restrict__ B,
                             float* __restrict__ C, int M, int N, int K)
{
    int idx = blockIdx.x * blockDim.x + threadIdx.x;
    if (idx >= M * N) return;
    int m = idx / N, n = idx % N;
    float s = 0.f;
    for (int k = 0; k < K; k++) s += A[(size_t)m * K + k] * B[(size_t)k * N + n];
    C[idx] = s;
}

// ---------------- weight builders (batched over layers) ----------------
__global__ void build_cbig_k(float* __restrict__ dst, const float* __restrict__ re,
                             const float* __restrict__ im, int Kd, int Nd)
{
    int l = blockIdx.y;
    dst += (size_t)l * (4 * Kd * Nd);
    re += (size_t)l * Kd * Nd;
    im += (size_t)l * Kd * Nd;
    int idx = blockIdx.x * blockDim.x + threadIdx.x;
    int N2 = 2 * Nd;
    if (idx >= 2 * Kd * N2) return;
    int k2 = idx / N2, n2 = idx % N2;
    bool ki = k2 >= Kd, ni = n2 >= Nd;
    int k = ki ? k2 - Kd : k2;
    int n = ni ? n2 - Nd : n2;
    float v;
    if (!ki && !ni) v = re[(size_t)k * Nd + n];
    else if (!ki && ni) v = im[(size_t)k * Nd + n];
    else if (ki && !ni) v = -im[(size_t)k * Nd + n];
    else v = re[(size_t)k * Nd + n];
    dst[idx] = v;
}

__global__ void build_cbigT_tile_k(hf* __restrict__ d0,
                                   const float* __restrict__ re, const float* __restrict__ im,
                                   int Kd, int Nd)
{
    __shared__ float tile[32][33];
    int l = blockIdx.z;
    d0 += (size_t)l * (4 * Kd * Nd);
    re += (size_t)l * Kd * Nd;
    im += (size_t)l * Kd * Nd;
    int k2_0 = blockIdx.x * 32, n2_0 = blockIdx.y * 32;
    bool ki = k2_0 >= Kd, ni = n2_0 >= Nd;
    int k0 = k2_0 - (ki ? Kd : 0), n0 = n2_0 - (ni ? Nd : 0);
    const float* s = (ki != ni) ? im : re;
    float sign = (ki && !ni) ? -1.f : 1.f;
    int tx = threadIdx.x, ty = threadIdx.y;
#pragma unroll
    for (int j = 0; j < 4; j++) {
        int r = ty + j * 8;
        tile[r][tx] = s[(size_t)(k0 + r) * Nd + n0 + tx];
    }
    __syncthreads();
    int K2 = 2 * Kd;
#pragma unroll
    for (int j = 0; j < 4; j++) {
        int r = ty + j * 8;
        float v = sign * tile[tx][r];
        d0[(size_t)(n2_0 + r) * K2 + k2_0 + tx] = __float2half(v);
    }
}

__global__ void build_convwT_k(hf* __restrict__ d0, const float* __restrict__ cw)
{
    __shared__ float s[KC];
    int co = blockIdx.x, l = blockIdx.y;
    const float* srcr = cw + ((size_t)(l * C2 + co)) * KC;
    for (int i = threadIdx.x; i < KC; i += 256) s[i] = srcr[i];
    __syncthreads();
    size_t base = ((size_t)l * C2 + co) * KC;
    for (int k = threadIdx.x; k < KC; k += 256) {
        int rs = k / 768;
        int ci = k - rs * 768;
        d0[base + k] = __float2half(s[ci * 9 + rs]);
    }
}

__global__ void cvt4_k(const float* __restrict__ src, hf* __restrict__ d0, size_t n4)
{
    size_t idx = (size_t)blockIdx.x * blockDim.x + threadIdx.x;
    if (idx >= n4) return;
    float4 v = ((const float4*)src)[idx];
    __half2 p0 = {__float2half(v.x), __float2half(v.y)};
    __half2 p1 = {__float2half(v.z), __float2half(v.w)};
    ((__half2*)d0)[idx * 2] = p0;
    ((__half2*)d0)[idx * 2 + 1] = p1;
}

// ---------------- encoder im2col (vectorized x4, fp16) ----------------
__global__ void enc_im2col4_k(hf* __restrict__ P0, const float* __restrict__ x)
{
    size_t idx = (size_t)blockIdx.x * blockDim.x + threadIdx.x;  // NP*KENC/4
    size_t flat = idx * 4;
    int kk = flat % KENC;
    int n = flat / KENC;
    int cin = kk >> 8;
    int ii = (kk >> 4) & 15;
    int jj = kk & 15;
    int bt = n >> 8;
    int ph = (n >> 4) & 15;
    int pw = n & 15;
    const float* xp = x + ((((size_t)(bt * 4 + cin) * 256) + ph * 16 + ii) * 256 + pw * 16 + jj);
    float4 v = *(const float4*)xp;
    __half2 p0 = {__float2half(v.x), __float2half(v.y)};
    __half2 p1 = {__float2half(v.z), __float2half(v.w)};
    ((__half2*)P0)[idx * 2] = p0;
    ((__half2*)P0)[idx * 2 + 1] = p1;
}

// ---------------- layernorm over 768 channels, emits fp16 ----------------
__global__ void layernorm_k(const float* __restrict__ X, const float* __restrict__ g,
                            const float* __restrict__ b, hf* __restrict__ Y0)
{
    __shared__ float red[256];
    int n = blockIdx.x;
    int tid = threadIdx.x;
    const float* x = X + (size_t)n * C2;
    float v0 = x[tid], v1 = x[tid + 256], v2 = x[tid + 512];
    red[tid] = v0 + v1 + v2;
    __syncthreads();
    for (int off = 128; off > 0; off >>= 1) {
        if (tid < off) red[tid] += red[tid + off];
        __syncthreads();
    }
    float m = red[0] * (1.f / 768.f);
    __syncthreads();
    float d0 = v0 - m, d1 = v1 - m, d2 = v2 - m;
    red[tid] = d0 * d0 + d1 * d1 + d2 * d2;
    __syncthreads();
    for (int off = 128; off > 0; off >>= 1) {
        if (tid < off) red[tid] += red[tid + off];
        __syncthreads();
    }
    float var = red[0] * (1.f / 768.f);
    float rstd = rsqrtf(var + 1e-5f);
    size_t base = (size_t)n * C2;
    Y0[base + tid]       = __float2half(d0 * rstd * g[tid] + b[tid]);
    Y0[base + tid + 256] = __float2half(d1 * rstd * g[tid + 256] + b[tid + 256]);
    Y0[base + tid + 512] = __float2half(d2 * rstd * g[tid + 512] + b[tid + 512]);
}

// ---------------- mean over 256 spatial positions (parallel + atomic) ----------------
__global__ void xmzero_k(float* __restrict__ xm)
{
    xm[blockIdx.x * 256 + threadIdx.x] = 0.f;
}
// grid (BT, 8), block 768: each block sums 32 hw positions for all channels.
__global__ void rowmean_k(const float* __restrict__ XE, float* __restrict__ xm)
{
    int bt = blockIdx.x;
    int seg = blockIdx.y;
    int c = threadIdx.x;
    float s = 0.f;
    const float* p = XE + ((size_t)bt * 256 + seg * 32) * C2 + c;
    for (int hw = 0; hw < 32; hw++) s += p[(size_t)hw * C2];
    atomicAdd(&xm[bt * C2 + c], s * (1.f / 256.f));
}

// ---------------- flux scan + gate + op_decay/op_forcing (merged) ----------------
__global__ void fluxscan_k(const float* __restrict__ xm, const float* __restrict__ dt,
                           const float* __restrict__ lamf_p, const float* __restrict__ Wg,
                           const float* __restrict__ nu, const float* __restrict__ omega,
                           float* __restrict__ flux, float* __restrict__ gate,
                           float* __restrict__ OD, float* __restrict__ OF)
{
    int tid = blockIdx.x * blockDim.x + threadIdx.x;  // BB*DD = 1536
    int b = tid / DD, e = tid % DD;
    float lamf = softplus_f(lamf_p[e]);
    float wg = Wg[e];
    float sp = softplus_f(nu[e]);
    float lr = fminf(fmaxf(-sp, -5.f), 0.3f);
    float li = omega[e];
    float den = lr * lr + li * li;
    float fr = 0.f, fi = 0.f;
    for (int t = 0; t < TT; t++) {
        int bt = b * TT + t;
        float dtv = dt[bt];
        float a = expf(-lamf * dtv);
        float xr = xm[bt * C2 + e] * dtv;
        float xi = xm[bt * C2 + DD + e] * dtv;
        fr = fr * a + xr;
        fi = fi * a + xi;
        flux[bt * C2 + e] = fr;
        flux[bt * C2 + DD + e] = fi;
        gate[bt * DD + e] = 1.f / (1.f + expf(-fr * wg));
        float er = expf(lr * dtv);
        float odr = er * cosf(li * dtv);
        float odi = er * sinf(li * dtv);
        OD[bt * C2 + e] = odr;
        OD[bt * C2 + DD + e] = odi;
        float nr = odr - 1.f, ni = odi;
        OF[bt * C2 + e] = (nr * lr + ni * li) / den;
        OF[bt * C2 + DD + e] = (ni * lr - nr * li) / den;
    }
}

// ---------------- fused forcing + u scan, emits fp16 ----------------
__global__ void fuscan_k(const float* __restrict__ XE, const float* __restrict__ gate,
                         const float* __restrict__ src, const float* __restrict__ OF,
                         const float* __restrict__ OD, hf* __restrict__ U0)
{
    int tid = blockIdx.x * blockDim.x + threadIdx.x;  // BB*256*DD
    int e = tid % DD;
    int hw = (tid / DD) & 255;
    int b = tid / (DD * 256);
    float ur = 0.f, ui = 0.f;
    for (int t = 0; t < TT; t++) {
        int bt = b * TT + t;
        size_t base = (size_t)(bt * 256 + hw) * C2;
        float xr = XE[base + e], xi = XE[base + DD + e];
        float g = gate[bt * DD + e];
        float sr = src[bt * C2 + e], si = src[bt * C2 + DD + e];
        float fr = xr * g + sr * (1.f - g);
        float fi = xi * g + si * (1.f - g);
        float ofr = OF[bt * C2 + e], ofi = OF[bt * C2 + DD + e];
        float utr = fr * ofr - fi * ofi;
        float uti = fr * ofi + fi * ofr;
        float odr = OD[bt * C2 + e], odi = OD[bt * C2 + DD + e];
        float nr = ur * odr - ui * odi + utr;
        float ni = ur * odi + ui * odr + uti;
        ur = nr; ui = ni;
        U0[base + e] = __float2half(ur);
        U0[base + DD + e] = __float2half(ui);
    }
}

// ---------------- host side ----------------
template <typename T>
static T* sym(const void* s)
{
    void* p = nullptr;
    cudaGetSymbolAddress(&p, s);
    return (T*)p;
}

template <int MODE, bool CONV>
static void launch_gemm(const hf* A0, const hf* B,
                        float* C, hf* C0, const float* Caux,
                        const float* bias, int N, int K)
{
    cudaFuncSetAttribute(hgemm_k<MODE, CONV>, cudaFuncAttributeMaxDynamicSharedMemorySize, SMEM_TOTAL_G);
    dim3 grid(N / 128, NP / 256);
    hgemm_k<MODE, CONV><<<grid, 256, SMEM_TOTAL_G>>>(A0, B, C, C0, Caux, bias, N, K);
}

extern "C" void kernel_launch(void* const* d_in, const int* in_sizes, int n_in,
                              void* d_out, int out_size)
{
    const float* x       = (const float*)d_in[0];
    const float* dt      = (const float*)d_in[1];
    const float* enc_w   = (const float*)d_in[2];
    const float* enc_b   = (const float*)d_in[3];
    const float* ns_g    = (const float*)d_in[4];
    const float* ns_b    = (const float*)d_in[5];
    const float* cw      = (const float*)d_in[6];
    const float* cb      = (const float*)d_in[7];
    const float* nt_g    = (const float*)d_in[8];
    const float* nt_b    = (const float*)d_in[9];
    const float* E_re    = (const float*)d_in[10];
    const float* E_im    = (const float*)d_in[11];
    const float* Ei_re   = (const float*)d_in[12];
    const float* Ei_im   = (const float*)d_in[13];
    const float* lamflux = (const float*)d_in[14];
    const float* Ws_re   = (const float*)d_in[15];
    const float* Ws_im   = (const float*)d_in[16];
    const float* Wg      = (const float*)d_in[17];
    const float* nu      = (const float*)d_in[18];
    const float* omega   = (const float*)d_in[19];
    const float* w1_re   = (const float*)d_in[20];
    const float* w1_im   = (const float*)d_in[21];
    const float* w2_re   = (const float*)d_in[22];
    const float* w2_im   = (const float*)d_in[23];
    const float* dec_w   = (const float*)d_in[24];
    const float* dec_b   = (const float*)d_in[25];
    float* out = (float*)d_out;

    float* Z   = sym<float>(g_Z);
    float* XE  = sym<float>(g_XE);
    float* DEC = sym<float>(g_DEC);
    hf* IM   = sym<hf>(g_IM);
    hf* Ab   = sym<hf>(g_Ab);
    hf* Zb   = sym<hf>(g_Zb);
    hf* Fb   = sym<hf>(g_Fb);
    hf* Hb   = sym<hf>(g_Hb);
    hf* Wcb  = sym<hf>(g_Wcb);
    hf* Eb   = sym<hf>(g_Eb);
    hf* Eib  = sym<hf>(g_Eib);
    hf* W1b  = sym<hf>(g_W1b);
    hf* W2b  = sym<hf>(g_W2b);
    hf* encb = sym<hf>(g_encb);
    hf* decb = sym<hf>(g_decb);
    float* Wsb  = sym<float>(g_Wsbig);
    float* xm   = sym<float>(g_xmean);
    float* flux = sym<float>(g_flux);
    float* src  = sym<float>(g_src);
    float* gate = sym<float>(g_gate);
    float* OD   = sym<float>(g_OD);
    float* OF   = sym<float>(g_OF);

    // ---- build weights (batched across layers) ----
    {
        dim3 blk(32, 8);
        build_cbigT_tile_k<<<dim3(C2 / 32, C2 / 32, LL), blk>>>(Eb, E_re, E_im, DD, DD);
        build_cbigT_tile_k<<<dim3(C2 / 32, C2 / 32, LL), blk>>>(Eib, Ei_re, Ei_im, DD, DD);
        build_cbig_k<<<dim3((C2 * C2) / 256, LL), 256>>>(Wsb, Ws_re, Ws_im, DD, DD);
        build_cbigT_tile_k<<<dim3(C2 / 32, DFF2 / 32, LL), blk>>>(W1b, w1_re, w1_im, DD, DFF);
        build_cbigT_tile_k<<<dim3(DFF2 / 32, C2 / 32, LL), blk>>>(W2b, w2_re, w2_im, DFF, DD);
        build_convwT_k<<<dim3(C2, LL), 256>>>(Wcb, cw);
        cvt4_k<<<(C2 * KENC / 4 + 255) / 256, 256>>>(enc_w, encb, (size_t)C2 * KENC / 4);
        cvt4_k<<<(NDEC * C2 / 4 + 255) / 256, 256>>>(dec_w, decb, (size_t)NDEC * C2 / 4);
    }

    // ---- encoder ----
    enc_im2col4_k<<<((size_t)NP * KENC / 4) / 256, 256>>>(IM, x);
    launch_gemm<1, false>(IM, encb, Z, nullptr, nullptr, enc_b, C2, KENC);

    for (int l = 0; l < LL; l++) {
        // spatial: LN -> implicit conv3x3 GEMM; Z += conv+cb, emit Zb fp16
        layernorm_k<<<NP, 256>>>(Z, ns_g + l * C2, ns_b + l * C2, Ab);
        launch_gemm<3, true>(Ab, Wcb + (size_t)l * C2 * KC, Z, Zb, nullptr, cb + l * C2, C2, KC);

        // spectral: XE = Z @ E
        launch_gemm<0, false>(Zb, Eb + (size_t)l * C2 * C2, XE, nullptr, nullptr, nullptr, C2, C2);

        // temporal flux path (fluxscan merged with opdecay)
        xmzero_k<<<(BT * C2) / 256, 256>>>(xm);
        rowmean_k<<<dim3(BT, 8), C2>>>(XE, xm);
        fluxscan_k<<<6, 256>>>(xm, dt, lamflux + l * DD, Wg + l * DD, nu + l * DD, omega + l * DD,
                               flux, gate, OD, OF);
        gemm_small_k<<<(BT * C2) / 256, 256>>>(flux, Wsb + (size_t)l * C2 * C2, src, BT, C2, C2);
        fuscan_k<<<(BB * 256 * DD) / 256, 256>>>(XE, gate, src, OF, OD, Ab);

        // decode back: DEC = u_out @ Ei
        launch_gemm<0, false>(Ab, Eib + (size_t)l * C2 * C2, DEC, nullptr, nullptr, nullptr, C2, C2);

        // MLP on LN(DEC); Z += DEC + delta (fused, also emits fp16(Z) -> Fb)
        layernorm_k<<<NP, 256>>>(DEC, nt_g + l * C2, nt_b + l * C2, Zb);
        launch_gemm<4, false>(Zb, W1b + (size_t)l * DFF2 * C2, nullptr, Hb, nullptr, nullptr, DFF2, C2);
        launch_gemm<6, false>(Hb, W2b + (size_t)l * C2 * DFF2, Z, Fb, DEC, nullptr, C2, DFF2);
    }

    // ---- decoder GEMM with fused pixel-shuffle scatter (input: Fb from last Z-fuse) ----
    launch_gemm<7, false>(Fb, decb, out, nullptr, nullptr, dec_b, NDEC, C2);

    (void)in_sizes; (void)n_in; (void)out_size;
}

// round 17
// speedup vs baseline: 1.0271x; 1.0105x over previous
#include <cuda_runtime.h>
#include <cuda_fp16.h>
#include <math.h>
#include <stdint.h>

// ---------------- constants ----------------
#define BB 4
#define TT 12
#define BT 48
#define DD 384
#define C2 768
#define NP 12288
#define KC 6912
#define DFF 1536
#define DFF2 3072
#define KENC 1024
#define NDEC 1024
#define LL 4

typedef __half hf;

// ---------------- device scratch ----------------
__device__ float g_Z[(size_t)NP * C2];
__device__ float g_XE[(size_t)NP * C2];
__device__ float g_DEC[(size_t)NP * C2];
__device__ hf g_IM[(size_t)NP * KENC];
__device__ hf g_Ab[(size_t)NP * C2];
__device__ hf g_Zb[(size_t)NP * C2];
__device__ hf g_Fb[(size_t)NP * C2];      // fp16 of final Z (decoder input)
__device__ hf g_Hb[(size_t)NP * DFF2];
__device__ hf g_Wcb[(size_t)LL * C2 * KC];
__device__ hf g_Eb[(size_t)LL * C2 * C2];
__device__ hf g_Eib[(size_t)LL * C2 * C2];
__device__ hf g_W1b[(size_t)LL * DFF2 * C2];   // [N=3072][K=768]
__device__ hf g_W2b[(size_t)LL * C2 * DFF2];   // [N=768][K=3072]
__device__ hf g_encb[C2 * KENC];
__device__ hf g_decb[NDEC * C2];
__device__ float g_Wsbig[(size_t)LL * C2 * C2];
__device__ float g_xm8[8 * BT * C2];           // per-segment rowmean partials
__device__ float g_flux[BT * C2];
__device__ float g_src[BT * C2];
__device__ float g_gate[BT * DD];
__device__ float g_OD[BT * C2];
__device__ float g_OF[BT * C2];

// ---------------- helpers ----------------
__device__ __forceinline__ float softplus_f(float x) {
    return (x > 20.f) ? x : log1pf(expf(x));
}
__device__ __forceinline__ float gelu_tanh(float x) {
    float x3 = x * x * x;
    float t = tanhf(0.7978845608028654f * (x + 0.044715f * x3));
    return 0.5f * x * (1.f + t);
}
__device__ __forceinline__ uint32_t smem_u32(const void* p) {
    uint32_t a;
    asm("{ .reg .u64 t; cvta.to.shared.u64 t, %1; cvt.u32.u64 %0, t; }" : "=r"(a) : "l"(p));
    return a;
}
__device__ __forceinline__ void cp16(uint32_t dst, const void* src) {
    asm volatile("cp.async.cg.shared.global [%0], [%1], 16;" :: "r"(dst), "l"(src) : "memory");
}
__device__ __forceinline__ void cp16z(uint32_t dst, const void* src, uint32_t sz) {
    asm volatile("cp.async.cg.shared.global [%0], [%1], 16, %2;" :: "r"(dst), "l"(src), "r"(sz) : "memory");
}
#define CP_COMMIT() asm volatile("cp.async.commit_group;" ::: "memory")

#define LDSM4(r, addr) \
    asm volatile("ldmatrix.sync.aligned.m8n8.x4.shared.b16 {%0,%1,%2,%3}, [%4];" \
                 : "=r"((r)[0]), "=r"((r)[1]), "=r"((r)[2]), "=r"((r)[3]) : "r"(addr))

#define MMA16816(d, a, bb0, bb1) \
    asm volatile("mma.sync.aligned.m16n8k16.row.col.f32.f16.f16.f32 " \
                 "{%0,%1,%2,%3}, {%4,%5,%6,%7}, {%8,%9}, {%0,%1,%2,%3};" \
                 : "+f"((d)[0]), "+f"((d)[1]), "+f"((d)[2]), "+f"((d)[3]) \
                 : "r"((a)[0]), "r"((a)[1]), "r"((a)[2]), "r"((a)[3]), \
                   "r"(bb0), "r"(bb1))

// ---------------- warp-MMA fp16 GEMM (single product, 3-stage, 1 barrier/chunk) ----------------
// C[M=12288, N] = A @ B^T, A and B single fp16.
// Block tile 256x128x32, 8 warps (4M x 2N), warp tile 64x64.
// smem/stage: A 256x80B=20480 + B 128x80B=10240 -> 30720B; x3 stages = 92160B.
// grid: x = N/128 (fast -> A tile L2 reuse), y = M/256.
// Pipeline invariant (single barrier): at iter c, wait_group(1) proves group c
// complete (only c+1 may be pending); the barrier publishes buf c AND orders
// iter c-1's LDSM reads of buf (c-1)%3 before this iter's cp.async writes to
// buf (c+2)%3 == (c-1)%3. Loads are issued AFTER the barrier.
// MODE: 0 store, 1 store+bias, 3 acc+bias+hf-emit, 4 gelu->hf, 6 Z-fuse+hf-emit, 7 dec-scatter
// CONV: implicit 3x3 im2col from A [NP][C2] (K = 9*768); spatial math hoisted.
// NOTE: load_chunk takes k0 as an ELEMENT offset (chunk << 5) — cp.async 16B
// alignment depends on it (R11 regression: passing a chunk index misaligns src).
#define MATA_B 20480
#define STAGE_B 30720
#define SMEM_TOTAL_G (3 * STAGE_B)

template <int MODE, bool CONV>
__global__ __launch_bounds__(256) void hgemm_k(
    const hf* __restrict__ A0, const hf* __restrict__ B,
    float* __restrict__ C, hf* __restrict__ C0,
    const float* __restrict__ Caux, const float* __restrict__ bias, int N, int K)
{
    extern __shared__ char smem[];
    uint32_t sb = smem_u32(smem);
    const int tid = threadIdx.x;
    const int wid = tid >> 5;
    const int lane = tid & 31;
    const int n0 = blockIdx.x * 128;
    const int m0 = blockIdx.y * 256;
    const int wm = wid & 3;       // 0..3 (M, x64)
    const int wn = wid >> 2;      // 0..1 (N, x64)

    // CONV precompute: per-slot row pointer and spatial coords.
    const hf* rowA[4];
    int hA[4], wA[4];
    if (CONV) {
#pragma unroll
        for (int i = 0; i < 4; i++) {
            int m = m0 + (tid >> 2) + 64 * i;
            hA[i] = (m >> 4) & 15;
            wA[i] = m & 15;
            rowA[i] = A0 + (size_t)m * 768 + (tid & 3) * 8;
        }
    }

    auto load_chunk = [&](int k0, int buf) {
        uint32_t st = sb + buf * STAGE_B;
        if (CONV) {
            int rs = k0 / 768;               // uniform across chunk
            int ci0 = k0 - rs * 768;
            int dy = rs / 3 - 1, dx = rs - (rs / 3) * 3 - 1;
            intptr_t doff = (intptr_t)(dy * 16 + dx) * 768 + ci0;
#pragma unroll
            for (int i = 0; i < 4; i++) {
                uint32_t dst = st + ((tid >> 2) + 64 * i) * 80 + (tid & 3) * 16;
                int hh = hA[i] + dy, ww = wA[i] + dx;
                bool ok = ((unsigned)hh < 16u) && ((unsigned)ww < 16u);
                const hf* sp = ok ? (rowA[i] + doff) : A0;
                cp16z(dst, sp, ok ? 16u : 0u);
            }
        } else {
#pragma unroll
            for (int i = 0; i < 4; i++) {
                int id = tid + 256 * i;
                int row = id >> 2, c4 = id & 3;
                uint32_t dst = st + row * 80 + c4 * 16;
                cp16(dst, A0 + (size_t)(m0 + row) * K + k0 + c4 * 8);
            }
        }
#pragma unroll
        for (int i = 0; i < 2; i++) {
            int id = tid + 256 * i;
            int row = id >> 2, c4 = id & 3;
            uint32_t dst = st + MATA_B + row * 80 + c4 * 16;
            cp16(dst, B + (size_t)(n0 + row) * K + k0 + c4 * 8);
        }
    };

    float acc[4][8][4];
#pragma unroll
    for (int i = 0; i < 4; i++)
#pragma unroll
        for (int j = 0; j < 8; j++)
#pragma unroll
            for (int e = 0; e < 4; e++) acc[i][j][e] = 0.f;

    const int nc = K >> 5;   // all GEMMs have nc >= 24
    load_chunk(0, 0);
    CP_COMMIT();
    load_chunk(32, 1);
    CP_COMMIT();

    const int lrow = lane & 15;
    const int lcol = lane >> 4;

    for (int c = 0; c < nc; c++) {
        int buf = c % 3;
        if (c + 1 < nc) {
            asm volatile("cp.async.wait_group 1;" ::: "memory");
        } else {
            asm volatile("cp.async.wait_group 0;" ::: "memory");
        }
        __syncthreads();
        if (c + 2 < nc) {
            load_chunk((c + 2) << 5, (c + 2) % 3);
            CP_COMMIT();
        }
        uint32_t st = sb + buf * STAGE_B;
#pragma unroll
        for (int ks = 0; ks < 2; ks++) {
            uint32_t a0[4][4];
#pragma unroll
            for (int mi = 0; mi < 4; mi++) {
                uint32_t ad = st + (wm * 64 + mi * 16 + lrow) * 80 + ks * 32 + lcol * 16;
                LDSM4(a0[mi], ad);
            }
#pragma unroll
            for (int nq = 0; nq < 4; nq++) {
                uint32_t br[4];
                uint32_t bd = st + MATA_B + (wn * 64 + nq * 16 + lrow) * 80 + ks * 32 + lcol * 16;
                LDSM4(br, bd);
#pragma unroll
                for (int mi = 0; mi < 4; mi++) {
                    MMA16816(acc[mi][nq * 2],     a0[mi], br[0], br[2]);
                    MMA16816(acc[mi][nq * 2 + 1], a0[mi], br[1], br[3]);
                }
            }
        }
    }

    // epilogue (vectorized: float2 / half2)
#pragma unroll
    for (int mi = 0; mi < 4; mi++) {
#pragma unroll
        for (int nj = 0; nj < 8; nj++) {
            int row = m0 + wm * 64 + mi * 16 + (lane >> 2);
            int col = n0 + wn * 64 + nj * 8 + (lane & 3) * 2;
            float* d = acc[mi][nj];
#pragma unroll
            for (int h = 0; h < 2; h++) {
                int r = row + h * 8;
                float v0 = d[h * 2 + 0], v1 = d[h * 2 + 1];
                if (MODE == 1 || MODE == 3 || MODE == 7) {
                    v0 += bias[col];
                    v1 += bias[col + 1];
                }
                size_t co = (size_t)r * N + col;
                if (MODE == 0 || MODE == 1) {
                    *(float2*)(C + co) = make_float2(v0, v1);
                } else if (MODE == 3) {
                    float2 zc = *(const float2*)(C + co);
                    float z0 = zc.x + v0, z1 = zc.y + v1;
                    *(float2*)(C + co) = make_float2(z0, z1);
                    *(__half2*)(C0 + co) = __floats2half2_rn(z0, z1);
                } else if (MODE == 4) {
                    *(__half2*)(C0 + co) = __floats2half2_rn(gelu_tanh(v0), gelu_tanh(v1));
                } else if (MODE == 6) {
                    float2 ax = *(const float2*)(Caux + co);
                    float2 zc = *(const float2*)(C + co);
                    float z0 = zc.x + ax.x + v0, z1 = zc.y + ax.y + v1;
                    *(float2*)(C + co) = make_float2(z0, z1);
                    *(__half2*)(C0 + co) = __floats2half2_rn(z0, z1);
                } else if (MODE == 7) {
                    // pixel-shuffle scatter: r -> (bt,hp,wp), col -> (co4,pi,pj)
                    int bt = r >> 8;
                    int hp = (r >> 4) & 15, wp = r & 15;
                    int co4 = col >> 8;
                    int rem = col & 255;
                    int pi = rem >> 4, pj = rem & 15;
                    size_t o = (((size_t)(bt * 4 + co4) * 256 + hp * 16 + pi) * 256) + wp * 16 + pj;
                    *(float2*)(C + o) = make_float2(v0, v1);
                }
            }
        }
    }
}

// ---------------- tiny fp32 GEMM (M=48) ----------------
__global__ void gemm_small_k(const float* __restrict__ A, const float* __restrict__ B,
                             float* __restrict__ C, int M, int N, int K)
{
    int idx = blockIdx.x * blockDim.x + threadIdx.x;
    if (idx >= M * N) return;
    int m = idx / N, n = idx % N;
    float s = 0.f;
    for (int k = 0; k < K; k++) s += A[(size_t)m * K + k] * B[(size_t)k * N + n];
    C[idx] = s;
}

// ---------------- weight builders (batched over layers) ----------------
__global__ void build_cbig_k(float* __restrict__ dst, const float* __restrict__ re,
                             const float* __restrict__ im, int Kd, int Nd)
{
    int l = blockIdx.y;
    dst += (size_t)l * (4 * Kd * Nd);
    re += (size_t)l * Kd * Nd;
    im += (size_t)l * Kd * Nd;
    int idx = blockIdx.x * blockDim.x + threadIdx.x;
    int N2 = 2 * Nd;
    if (idx >= 2 * Kd * N2) return;
    int k2 = idx / N2, n2 = idx % N2;
    bool ki = k2 >= Kd, ni = n2 >= Nd;
    int k = ki ? k2 - Kd : k2;
    int n = ni ? n2 - Nd : n2;
    float v;
    if (!ki && !ni) v = re[(size_t)k * Nd + n];
    else if (!ki && ni) v = im[(size_t)k * Nd + n];
    else if (ki && !ni) v = -im[(size_t)k * Nd + n];
    else v = re[(size_t)k * Nd + n];
    dst[idx] = v;
}

__global__ void build_cbigT_tile_k(hf* __restrict__ d0,
                                   const float* __restrict__ re, const float* __restrict__ im,
                                   int Kd, int Nd)
{
    __shared__ float tile[32][33];
    int l = blockIdx.z;
    d0 += (size_t)l * (4 * Kd * Nd);
    re += (size_t)l * Kd * Nd;
    im += (size_t)l * Kd * Nd;
    int k2_0 = blockIdx.x * 32, n2_0 = blockIdx.y * 32;
    bool ki = k2_0 >= Kd, ni = n2_0 >= Nd;
    int k0 = k2_0 - (ki ? Kd : 0), n0 = n2_0 - (ni ? Nd : 0);
    const float* s = (ki != ni) ? im : re;
    float sign = (ki && !ni) ? -1.f : 1.f;
    int tx = threadIdx.x, ty = threadIdx.y;
#pragma unroll
    for (int j = 0; j < 4; j++) {
        int r = ty + j * 8;
        tile[r][tx] = s[(size_t)(k0 + r) * Nd + n0 + tx];
    }
    __syncthreads();
    int K2 = 2 * Kd;
#pragma unroll
    for (int j = 0; j < 4; j++) {
        int r = ty + j * 8;
        float v = sign * tile[tx][r];
        d0[(size_t)(n2_0 + r) * K2 + k2_0 + tx] = __float2half(v);
    }
}

__global__ void build_convwT_k(hf* __restrict__ d0, const float* __restrict__ cw)
{
    __shared__ float s[KC];
    int co = blockIdx.x, l = blockIdx.y;
    const float* srcr = cw + ((size_t)(l * C2 + co)) * KC;
    for (int i = threadIdx.x; i < KC; i += 256) s[i] = srcr[i];
    __syncthreads();
    size_t base = ((size_t)l * C2 + co) * KC;
    for (int k = threadIdx.x; k < KC; k += 256) {
        int rs = k / 768;
        int ci = k - rs * 768;
        d0[base + k] = __float2half(s[ci * 9 + rs]);
    }
}

__global__ void cvt4_k(const float* __restrict__ src, hf* __restrict__ d0, size_t n4)
{
    size_t idx = (size_t)blockIdx.x * blockDim.x + threadIdx.x;
    if (idx >= n4) return;
    float4 v = ((const float4*)src)[idx];
    __half2 p0 = {__float2half(v.x), __float2half(v.y)};
    __half2 p1 = {__float2half(v.z), __float2half(v.w)};
    ((__half2*)d0)[idx * 2] = p0;
    ((__half2*)d0)[idx * 2 + 1] = p1;
}

// ---------------- encoder im2col (vectorized x4, fp16) ----------------
__global__ void enc_im2col4_k(hf* __restrict__ P0, const float* __restrict__ x)
{
    size_t idx = (size_t)blockIdx.x * blockDim.x + threadIdx.x;  // NP*KENC/4
    size_t flat = idx * 4;
    int kk = flat % KENC;
    int n = flat / KENC;
    int cin = kk >> 8;
    int ii = (kk >> 4) & 15;
    int jj = kk & 15;
    int bt = n >> 8;
    int ph = (n >> 4) & 15;
    int pw = n & 15;
    const float* xp = x + ((((size_t)(bt * 4 + cin) * 256) + ph * 16 + ii) * 256 + pw * 16 + jj);
    float4 v = *(const float4*)xp;
    __half2 p0 = {__float2half(v.x), __float2half(v.y)};
    __half2 p1 = {__float2half(v.z), __float2half(v.w)};
    ((__half2*)P0)[idx * 2] = p0;
    ((__half2*)P0)[idx * 2 + 1] = p1;
}

// ---------------- layernorm over 768 channels (shuffle reduce), emits fp16 ----------------
__global__ void layernorm_k(const float* __restrict__ X, const float* __restrict__ g,
                            const float* __restrict__ b, hf* __restrict__ Y0)
{
    __shared__ float red[8];
    int n = blockIdx.x;
    int tid = threadIdx.x;
    int lane = tid & 31, wid = tid >> 5;
    const float* x = X + (size_t)n * C2;
    float v0 = x[tid], v1 = x[tid + 256], v2 = x[tid + 512];

    float s = v0 + v1 + v2;
#pragma unroll
    for (int off = 16; off > 0; off >>= 1) s += __shfl_xor_sync(0xffffffffu, s, off);
    if (lane == 0) red[wid] = s;
    __syncthreads();
    float m = 0.f;
#pragma unroll
    for (int i = 0; i < 8; i++) m += red[i];
    m *= (1.f / 768.f);

    float d0 = v0 - m, d1 = v1 - m, d2 = v2 - m;
    float q = d0 * d0 + d1 * d1 + d2 * d2;
#pragma unroll
    for (int off = 16; off > 0; off >>= 1) q += __shfl_xor_sync(0xffffffffu, q, off);
    __syncthreads();                 // protect red[] reuse
    if (lane == 0) red[wid] = q;
    __syncthreads();
    float var = 0.f;
#pragma unroll
    for (int i = 0; i < 8; i++) var += red[i];
    var *= (1.f / 768.f);
    float rstd = rsqrtf(var + 1e-5f);

    size_t base = (size_t)n * C2;
    Y0[base + tid]       = __float2half(d0 * rstd * g[tid] + b[tid]);
    Y0[base + tid + 256] = __float2half(d1 * rstd * g[tid + 256] + b[tid + 256]);
    Y0[base + tid + 512] = __float2half(d2 * rstd * g[tid + 512] + b[tid + 512]);
}

// ---------------- mean over 256 spatial positions (8 disjoint partials) ----------------
// grid (BT, 8), block 768: block (bt,seg) sums hw in [seg*32, seg*32+32).
__global__ void rowmean_k(const float* __restrict__ XE, float* __restrict__ xm8)
{
    int bt = blockIdx.x;
    int seg = blockIdx.y;
    int c = threadIdx.x;
    float s = 0.f;
    const float* p = XE + ((size_t)bt * 256 + seg * 32) * C2 + c;
    for (int hw = 0; hw < 32; hw++) s += p[(size_t)hw * C2];
    xm8[((size_t)seg * BT + bt) * C2 + c] = s;
}

// ---------------- flux scan + gate + op_decay/op_forcing (merged) ----------------
__global__ void fluxscan_k(const float* __restrict__ xm8, const float* __restrict__ dt,
                           const float* __restrict__ lamf_p, const float* __restrict__ Wg,
                           const float* __restrict__ nu, const float* __restrict__ omega,
                           float* __restrict__ flux, float* __restrict__ gate,
                           float* __restrict__ OD, float* __restrict__ OF)
{
    int tid = blockIdx.x * blockDim.x + threadIdx.x;  // BB*DD = 1536
    int b = tid / DD, e = tid % DD;
    float lamf = softplus_f(lamf_p[e]);
    float wg = Wg[e];
    float sp = softplus_f(nu[e]);
    float lr = fminf(fmaxf(-sp, -5.f), 0.3f);
    float li = omega[e];
    float den = lr * lr + li * li;
    float fr = 0.f, fi = 0.f;
    for (int t = 0; t < TT; t++) {
        int bt = b * TT + t;
        float dtv = dt[bt];
        float a = expf(-lamf * dtv);
        // sum 8 rowmean partials (fixed order)
        float sxr = 0.f, sxi = 0.f;
#pragma unroll
        for (int sgm = 0; sgm < 8; sgm++) {
            size_t o = ((size_t)sgm * BT + bt) * C2;
            sxr += xm8[o + e];
            sxi += xm8[o + DD + e];
        }
        float xr = sxr * (1.f / 256.f) * dtv;
        float xi = sxi * (1.f / 256.f) * dtv;
        fr = fr * a + xr;
        fi = fi * a + xi;
        flux[bt * C2 + e] = fr;
        flux[bt * C2 + DD + e] = fi;
        gate[bt * DD + e] = 1.f / (1.f + expf(-fr * wg));
        float er = expf(lr * dtv);
        float odr = er * cosf(li * dtv);
        float odi = er * sinf(li * dtv);
        OD[bt * C2 + e] = odr;
        OD[bt * C2 + DD + e] = odi;
        float nr = odr - 1.f, ni = odi;
        OF[bt * C2 + e] = (nr * lr + ni * li) / den;
        OF[bt * C2 + DD + e] = (ni * lr - nr * li) / den;
    }
}

// ---------------- fused forcing + u scan, emits fp16 ----------------
__global__ void fuscan_k(const float* __restrict__ XE, const float* __restrict__ gate,
                         const float* __restrict__ src, const float* __restrict__ OF,
                         const float* __restrict__ OD, hf* __restrict__ U0)
{
    int tid = blockIdx.x * blockDim.x + threadIdx.x;  // BB*256*DD
    int e = tid % DD;
    int hw = (tid / DD) & 255;
    int b = tid / (DD * 256);
    float ur = 0.f, ui = 0.f;
    for (int t = 0; t < TT; t++) {
        int bt = b * TT + t;
        size_t base = (size_t)(bt * 256 + hw) * C2;
        float xr = XE[base + e], xi = XE[base + DD + e];
        float g = gate[bt * DD + e];
        float sr = src[bt * C2 + e], si = src[bt * C2 + DD + e];
        float fr = xr * g + sr * (1.f - g);
        float fi = xi * g + si * (1.f - g);
        float ofr = OF[bt * C2 + e], ofi = OF[bt * C2 + DD + e];
        float utr = fr * ofr - fi * ofi;
        float uti = fr * ofi + fi * ofr;
        float odr = OD[bt * C2 + e], odi = OD[bt * C2 + DD + e];
        float nr = ur * odr - ui * odi + utr;
        float ni = ur * odi + ui * odr + uti;
        ur = nr; ui = ni;
        U0[base + e] = __float2half(ur);
        U0[base + DD + e] = __float2half(ui);
    }
}

// ---------------- host side ----------------
template <typename T>
static T* sym(const void* s)
{
    void* p = nullptr;
    cudaGetSymbolAddress(&p, s);
    return (T*)p;
}

template <int MODE, bool CONV>
static void launch_gemm(const hf* A0, const hf* B,
                        float* C, hf* C0, const float* Caux,
                        const float* bias, int N, int K)
{
    cudaFuncSetAttribute(hgemm_k<MODE, CONV>, cudaFuncAttributeMaxDynamicSharedMemorySize, SMEM_TOTAL_G);
    dim3 grid(N / 128, NP / 256);
    hgemm_k<MODE, CONV><<<grid, 256, SMEM_TOTAL_G>>>(A0, B, C, C0, Caux, bias, N, K);
}

extern "C" void kernel_launch(void* const* d_in, const int* in_sizes, int n_in,
                              void* d_out, int out_size)
{
    const float* x       = (const float*)d_in[0];
    const float* dt      = (const float*)d_in[1];
    const float* enc_w   = (const float*)d_in[2];
    const float* enc_b   = (const float*)d_in[3];
    const float* ns_g    = (const float*)d_in[4];
    const float* ns_b    = (const float*)d_in[5];
    const float* cw      = (const float*)d_in[6];
    const float* cb      = (const float*)d_in[7];
    const float* nt_g    = (const float*)d_in[8];
    const float* nt_b    = (const float*)d_in[9];
    const float* E_re    = (const float*)d_in[10];
    const float* E_im    = (const float*)d_in[11];
    const float* Ei_re   = (const float*)d_in[12];
    const float* Ei_im   = (const float*)d_in[13];
    const float* lamflux = (const float*)d_in[14];
    const float* Ws_re   = (const float*)d_in[15];
    const float* Ws_im   = (const float*)d_in[16];
    const float* Wg      = (const float*)d_in[17];
    const float* nu      = (const float*)d_in[18];
    const float* omega   = (const float*)d_in[19];
    const float* w1_re   = (const float*)d_in[20];
    const float* w1_im   = (const float*)d_in[21];
    const float* w2_re   = (const float*)d_in[22];
    const float* w2_im   = (const float*)d_in[23];
    const float* dec_w   = (const float*)d_in[24];
    const float* dec_b   = (const float*)d_in[25];
    float* out = (float*)d_out;

    float* Z   = sym<float>(g_Z);
    float* XE  = sym<float>(g_XE);
    float* DEC = sym<float>(g_DEC);
    hf* IM   = sym<hf>(g_IM);
    hf* Ab   = sym<hf>(g_Ab);
    hf* Zb   = sym<hf>(g_Zb);
    hf* Fb   = sym<hf>(g_Fb);
    hf* Hb   = sym<hf>(g_Hb);
    hf* Wcb  = sym<hf>(g_Wcb);
    hf* Eb   = sym<hf>(g_Eb);
    hf* Eib  = sym<hf>(g_Eib);
    hf* W1b  = sym<hf>(g_W1b);
    hf* W2b  = sym<hf>(g_W2b);
    hf* encb = sym<hf>(g_encb);
    hf* decb = sym<hf>(g_decb);
    float* Wsb  = sym<float>(g_Wsbig);
    float* xm8  = sym<float>(g_xm8);
    float* flux = sym<float>(g_flux);
    float* src  = sym<float>(g_src);
    float* gate = sym<float>(g_gate);
    float* OD   = sym<float>(g_OD);
    float* OF   = sym<float>(g_OF);

    // ---- build weights (batched across layers) ----
    {
        dim3 blk(32, 8);
        build_cbigT_tile_k<<<dim3(C2 / 32, C2 / 32, LL), blk>>>(Eb, E_re, E_im, DD, DD);
        build_cbigT_tile_k<<<dim3(C2 / 32, C2 / 32, LL), blk>>>(Eib, Ei_re, Ei_im, DD, DD);
        build_cbig_k<<<dim3((C2 * C2) / 256, LL), 256>>>(Wsb, Ws_re, Ws_im, DD, DD);
        build_cbigT_tile_k<<<dim3(C2 / 32, DFF2 / 32, LL), blk>>>(W1b, w1_re, w1_im, DD, DFF);
        build_cbigT_tile_k<<<dim3(DFF2 / 32, C2 / 32, LL), blk>>>(W2b, w2_re, w2_im, DFF, DD);
        build_convwT_k<<<dim3(C2, LL), 256>>>(Wcb, cw);
        cvt4_k<<<(C2 * KENC / 4 + 255) / 256, 256>>>(enc_w, encb, (size_t)C2 * KENC / 4);
        cvt4_k<<<(NDEC * C2 / 4 + 255) / 256, 256>>>(dec_w, decb, (size_t)NDEC * C2 / 4);
    }

    // ---- encoder ----
    enc_im2col4_k<<<((size_t)NP * KENC / 4) / 256, 256>>>(IM, x);
    launch_gemm<1, false>(IM, encb, Z, nullptr, nullptr, enc_b, C2, KENC);

    for (int l = 0; l < LL; l++) {
        // spatial: LN -> implicit conv3x3 GEMM; Z += conv+cb, emit Zb fp16
        layernorm_k<<<NP, 256>>>(Z, ns_g + l * C2, ns_b + l * C2, Ab);
        launch_gemm<3, true>(Ab, Wcb + (size_t)l * C2 * KC, Z, Zb, nullptr, cb + l * C2, C2, KC);

        // spectral: XE = Z @ E
        launch_gemm<0, false>(Zb, Eb + (size_t)l * C2 * C2, XE, nullptr, nullptr, nullptr, C2, C2);

        // temporal flux path
        rowmean_k<<<dim3(BT, 8), C2>>>(XE, xm8);
        fluxscan_k<<<6, 256>>>(xm8, dt, lamflux + l * DD, Wg + l * DD, nu + l * DD, omega + l * DD,
                               flux, gate, OD, OF);
        gemm_small_k<<<(BT * C2) / 256, 256>>>(flux, Wsb + (size_t)l * C2 * C2, src, BT, C2, C2);
        fuscan_k<<<(BB * 256 * DD) / 256, 256>>>(XE, gate, src, OF, OD, Ab);

        // decode back: DEC = u_out @ Ei
        launch_gemm<0, false>(Ab, Eib + (size_t)l * C2 * C2, DEC, nullptr, nullptr, nullptr, C2, C2);

        // MLP on LN(DEC); Z += DEC + delta (fused, also emits fp16(Z) -> Fb)
        layernorm_k<<<NP, 256>>>(DEC, nt_g + l * C2, nt_b + l * C2, Zb);
        launch_gemm<4, false>(Zb, W1b + (size_t)l * DFF2 * C2, nullptr, Hb, nullptr, nullptr, DFF2, C2);
        launch_gemm<6, false>(Hb, W2b + (size_t)l * C2 * DFF2, Z, Fb, DEC, nullptr, C2, DFF2);
    }

    // ---- decoder GEMM with fused pixel-shuffle scatter (input: Fb from last Z-fuse) ----
    launch_gemm<7, false>(Fb, decb, out, nullptr, nullptr, dec_b, NDEC, C2);

    (void)in_sizes; (void)n_in; (void)out_size;
}